// round 3
// baseline (speedup 1.0000x reference)
#include <cuda_runtime.h>

typedef unsigned int u32;
typedef unsigned long long u64;

#define NB 32
#define NPTS 16384
#define NP 50
#define SUBN 128
#define NIT 30

__device__ u32 g_idx[2][SUBN];
__device__ float g_src[NB][SUBN][3];
__device__ float g_tgt[NB][SUBN][3];
__device__ float g_pop[2][NB][NP][6];
__device__ float g_fit[2][NB][NP];
__device__ unsigned char g_perm[NIT][3][NB][NP];
__device__ unsigned char g_mask[NIT][NB][NP];
__device__ float g_Rt[NB][12];

__device__ __forceinline__ u32 rotl32(u32 x, u32 r){ return (x<<r)|(x>>(32u-r)); }
__device__ __forceinline__ void tf2x32(u32 k0,u32 k1,u32 x0,u32 x1,u32&o0,u32&o1){
  u32 k2 = k0 ^ k1 ^ 0x1BD11BDAu;
  x0 += k0; x1 += k1;
#define TFR(r) { x0 += x1; x1 = rotl32(x1,(r)); x1 ^= x0; }
  TFR(13) TFR(15) TFR(26) TFR(6)   x0+=k1; x1+=k2+1u;
  TFR(17) TFR(29) TFR(16) TFR(24)  x0+=k2; x1+=k0+2u;
  TFR(13) TFR(15) TFR(26) TFR(6)   x0+=k0; x1+=k1+3u;
  TFR(17) TFR(29) TFR(16) TFR(24)  x0+=k1; x1+=k2+4u;
  TFR(13) TFR(15) TFR(26) TFR(6)   x0+=k2; x1+=k0+5u;
#undef TFR
  o0=x0; o1=x1;
}
struct Key { u32 a, b; };
// PARTITIONABLE threefry (JAX >= 0.4.36 default):
// split(key,n)[j] = both words of tf(key, 0, j)  (== fold_in(key, j))
__device__ __forceinline__ Key split_p(Key k, u32 j){
  Key r; tf2x32(k.a,k.b,0u,j,r.a,r.b); return r;
}
// random_bits(key,32,shape)[i] = o0 ^ o1 of tf(key, hi64(i)=0, lo64(i)=i)
__device__ __forceinline__ u32 rbits_p(Key k, u32 i){
  u32 o0,o1; tf2x32(k.a,k.b,0u,i,o0,o1); return o0^o1;
}
__device__ __forceinline__ float unif01(Key k, u32 i){
  u32 b = rbits_p(k,i);
  return __fsub_rn(__uint_as_float((b>>9)|0x3f800000u), 1.0f);
}

// ---- big permutation: 2-round stable sort-shuffle, one block per array ----
__global__ void k_bigperm(){
  extern __shared__ u64 sh[];
  const int tid = threadIdx.x, nth = blockDim.x;
  Key base; base.a=0u; base.b=42u;
  Key key = split_p(base, blockIdx.x);   // k0 or k1
  for(int round=0; round<2; round++){
    Key nk  = split_p(key,0);
    Key sub = split_p(key,1);
    key = nk;
    __syncthreads();
    for(int i=tid;i<NPTS;i+=nth){
      u32 pay = (round==0)? (u32)i : (u32)(sh[i] & 0x3FFFull);
      u32 bits = rbits_p(sub,(u32)i);
      sh[i] = ((u64)bits<<32) | ((u64)(u32)i<<14) | (u64)pay;
    }
    for(int k=2;k<=NPTS;k<<=1)
      for(int j=k>>1;j>0;j>>=1){
        __syncthreads();
        for(int p=tid;p<(NPTS>>1);p+=nth){
          int i = ((p & ~(j-1))<<1) | (p & (j-1));
          int l = i + j;
          u64 x = sh[i], y = sh[l];
          if( (x>y) == ((i&k)==0) ){ sh[i]=y; sh[l]=x; }
        }
      }
    __syncthreads();
  }
  for(int i=tid;i<SUBN;i+=nth) g_idx[blockIdx.x][i] = (u32)(sh[i]&0x3FFFull);
}

// ---- per-iteration RNG tables ----
__global__ void k_tables(){
  const int it = blockIdx.x, tid = threadIdx.x;
  Key base; base.a=0u; base.b=42u;
  Key kloop = split_p(base,4);
  Key kit   = split_p(kloop,(u32)it);
  Key ka    = split_p(kit,0);
  Key kb    = split_p(kit,1);
  Key kc    = split_p(kit,2);
  if(tid < 3*NB){
    Key pk  = split_p(ka,(u32)tid);
    Key sub = split_p(pk,1);           // key,subkey = split(kk); 1 round for P=50
    u64 arr[NP];
    for(int i=0;i<NP;i++) arr[i] = ((u64)rbits_p(sub,(u32)i)<<6) | (u64)(u32)i;
    for(int i=1;i<NP;i++){
      u64 v = arr[i]; int j = i-1;
      while(j>=0 && arr[j]>v){ arr[j+1]=arr[j]; j--; }
      arr[j+1]=v;
    }
    int r = tid>>5, b = tid&31;
    for(int i=0;i<NP;i++) g_perm[it][r][b][i] = (unsigned char)(arr[i]&63u);
  }
  Key kr1 = split_p(kc,0);   // higher_key
  Key kr2 = split_p(kc,1);   // lower_key
  for(int f=tid; f<NB*NP; f+=blockDim.x){
    u32 hi = rbits_p(kr1,(u32)f);
    u32 lo = rbits_p(kr2,(u32)f);
    u32 jr = ((hi%6u)*4u + (lo%6u)) % 6u;
    unsigned char m = 0;
    for(int d=0; d<6; d++){
      float u = unif01(kb,(u32)(f*6+d));
      if(u < 0.9f || (u32)d == jr) m |= (unsigned char)(1<<d);
    }
    g_mask[it][f/NP][f%NP] = m;
  }
}

// ---- gather subsets + init population ----
__global__ void k_init(const float* __restrict__ source, const float* __restrict__ target){
  const int gid = blockIdx.x*blockDim.x + threadIdx.x;
  if(gid < NB*SUBN*3){
    int d = gid%3, i = (gid/3)%SUBN, b = gid/(3*SUBN);
    g_src[b][i][d] = source[((size_t)b*NPTS + g_idx[0][i])*3 + d];
    g_tgt[b][i][d] = target[((size_t)b*NPTS + g_idx[1][i])*3 + d];
  }
  if(gid < NB*NP*3){
    Key base; base.a=0u; base.b=42u;
    Key k2 = split_p(base,2);
    Key k3 = split_p(base,3);
    int d = gid%3, p = (gid/3)%NP, b = gid/(3*NP);
    const float RR = 0.78539816339744830961f;
    float r = unif01(k2,(u32)gid);
    float t = unif01(k3,(u32)gid);
    r = fmaxf(-RR,   __fadd_rn(__fmul_rn(r, RR+RR), -RR));
    t = fmaxf(-1.0f, __fadd_rn(__fmul_rn(t, 2.0f), -1.0f));
    if(p==0){ r=0.0f; t=0.0f; }
    g_pop[0][b][p][d]   = r;
    g_pop[0][b][p][d+3] = t;
  }
}

// ---- rotation matrix (K@K via cuBLAS-style FMA chain, rest rn mul/add) ----
__device__ void compute_R(const float* v, float* R){
  float v0=v[0], v1=v[1], v2=v[2];
  float n2 = __fadd_rn(__fadd_rn(__fmul_rn(v0,v0),__fmul_rn(v1,v1)),__fmul_rn(v2,v2));
  float th = __fsqrt_rn(n2);
  float dn = fmaxf(th, 1e-8f);
  float kx = __fdiv_rn(v0,dn), ky = __fdiv_rn(v1,dn), kz = __fdiv_rn(v2,dn);
  float s = sinf(th), c = cosf(th);
  float omc = __fsub_rn(1.0f, c);
  float K[9] = {0.f,-kz,ky,  kz,0.f,-kx,  -ky,kx,0.f};
#pragma unroll
  for(int i=0;i<3;i++)
#pragma unroll
    for(int j=0;j<3;j++){
      float kk = __fmaf_rn(K[i*3+2],K[2*3+j],
                 __fmaf_rn(K[i*3+1],K[1*3+j],
                 __fmul_rn(K[i*3+0],K[0*3+j])));
      float iden = (i==j)?1.0f:0.0f;
      float r = __fadd_rn(__fadd_rn(iden, __fmul_rn(s,K[i*3+j])), __fmul_rn(omc,kk));
      R[i*3+j] = (th < 1e-8f) ? iden : r;
    }
}

struct ESm {
  float t[SUBN][3]; float yn[SUBN];
  float xs[SUBN][3]; float xn[SUBN];
  float ra[SUBN]; float ca[SUBN];
  float pose[6];
  float fit;
  int   imp;
};

// d2 = max((xn+yn) - 2*cross, 0), cross via FMA chain (gemm-style)
__device__ __forceinline__ float d2f(float x0,float x1,float x2,float xn,
                                     float y0,float y1,float y2,float yn){
  float dot = __fmaf_rn(x2,y2, __fmaf_rn(x1,y1, __fmul_rn(x0,y0)));
  return fmaxf(__fsub_rn(__fadd_rn(xn,yn), __fmul_rn(2.0f,dot)), 0.0f);
}

// Returns fit on lane 0 of warp 0; XLA row-reduce order (stride-32 partials + shfl tree)
__device__ float eval_pose(ESm& sm, int b, int n){
  float R[9];
  compute_R(sm.pose, R);
  float s0=g_src[b][n][0], s1=g_src[b][n][1], s2=g_src[b][n][2];
  float u0=g_tgt[b][n][0], u1=g_tgt[b][n][1], u2=g_tgt[b][n][2];
  sm.t[n][0]=u0; sm.t[n][1]=u1; sm.t[n][2]=u2;
  float ynv = __fadd_rn(__fadd_rn(__fmul_rn(u0,u0),__fmul_rn(u1,u1)),__fmul_rn(u2,u2));
  sm.yn[n]=ynv;
  float x0 = __fadd_rn(__fmaf_rn(s2,R[2], __fmaf_rn(s1,R[1], __fmul_rn(s0,R[0]))), sm.pose[3]);
  float x1 = __fadd_rn(__fmaf_rn(s2,R[5], __fmaf_rn(s1,R[4], __fmul_rn(s0,R[3]))), sm.pose[4]);
  float x2 = __fadd_rn(__fmaf_rn(s2,R[8], __fmaf_rn(s1,R[7], __fmul_rn(s0,R[6]))), sm.pose[5]);
  float xnv = __fadd_rn(__fadd_rn(__fmul_rn(x0,x0),__fmul_rn(x1,x1)),__fmul_rn(x2,x2));
  sm.xs[n][0]=x0; sm.xs[n][1]=x1; sm.xs[n][2]=x2; sm.xn[n]=xnv;
  __syncthreads();
  const float INF = __int_as_float(0x7f800000);
  float rmin = INF, cmin = INF;
#pragma unroll 4
  for(int m=0;m<SUBN;m++){
    rmin = fminf(rmin, d2f(x0,x1,x2,xnv, sm.t[m][0],sm.t[m][1],sm.t[m][2], sm.yn[m]));
    cmin = fminf(cmin, d2f(sm.xs[m][0],sm.xs[m][1],sm.xs[m][2],sm.xn[m], u0,u1,u2,ynv));
  }
  sm.ra[n]=rmin; sm.ca[n]=cmin;
  __syncthreads();
  float fit = 0.0f;
  if(n < 32){
    float pr = __fadd_rn(__fadd_rn(__fadd_rn(sm.ra[n], sm.ra[n+32]), sm.ra[n+64]), sm.ra[n+96]);
    float pc = __fadd_rn(__fadd_rn(__fadd_rn(sm.ca[n], sm.ca[n+32]), sm.ca[n+64]), sm.ca[n+96]);
#pragma unroll
    for(int o=16;o>0;o>>=1){
      pr = __fadd_rn(pr, __shfl_down_sync(0xffffffffu, pr, o));
      pc = __fadd_rn(pc, __shfl_down_sync(0xffffffffu, pc, o));
    }
    fit = __fadd_rn(__fmul_rn(pr,0.0078125f), __fmul_rn(pc,0.0078125f));
  }
  return fit;
}

__global__ void k_eval(){
  __shared__ ESm sm;
  const int b = blockIdx.x/NP, p = blockIdx.x%NP, n = threadIdx.x;
  if(n<6) sm.pose[n] = g_pop[0][b][p][n];
  __syncthreads();
  float f = eval_pose(sm,b,n);
  if(n==0) g_fit[0][b][p] = f;
}

__global__ void k_iter(int it, int sb){
  __shared__ ESm sm;
  const int b = blockIdx.x/NP, p = blockIdx.x%NP, n = threadIdx.x;
  const int db = sb^1;
  if(n==0){
    int r1 = g_perm[it][0][b][p], r2 = g_perm[it][1][b][p], r3 = g_perm[it][2][b][p];
    unsigned char m = g_mask[it][b][p];
    const float RR = 0.78539816339744830961f;
#pragma unroll
    for(int d=0; d<6; d++){
      float mu = __fadd_rn(g_pop[sb][b][r1][d],
                 __fmul_rn(0.8f, __fsub_rn(g_pop[sb][b][r2][d], g_pop[sb][b][r3][d])));
      float lim = (d<3) ? RR : 1.0f;
      mu = fminf(fmaxf(mu, -lim), lim);
      sm.pose[d] = ((m>>d)&1) ? mu : g_pop[sb][b][p][d];
    }
  }
  __syncthreads();
  float tf = eval_pose(sm,b,n);
  if(n==0){
    float of = g_fit[sb][b][p];
    int imp = (tf < of);
    sm.imp = imp;
    g_fit[db][b][p] = imp ? tf : of;
  }
  __syncthreads();
  if(n<6) g_pop[db][b][p][n] = sm.imp ? sm.pose[n] : g_pop[sb][b][p][n];
}

__global__ void k_final(int buf, float* __restrict__ out){
  const int b = threadIdx.x;
  if(b >= NB) return;
  float best = g_fit[buf][b][0]; int bi = 0;
  for(int p=1;p<NP;p++){ float f = g_fit[buf][b][p]; if(f < best){ best=f; bi=p; } }
  float pose[6];
  for(int d=0;d<6;d++) pose[d] = g_pop[buf][b][bi][d];
  float R[9]; compute_R(pose, R);
  for(int i=0;i<9;i++){ out[b*9+i] = R[i]; g_Rt[b][i] = R[i]; }
  for(int k=0;k<3;k++){ out[NB*9 + b*3 + k] = pose[3+k]; g_Rt[b][9+k] = pose[3+k]; }
}

__global__ void k_align(const float* __restrict__ source, float* __restrict__ out){
  long gid = (long)blockIdx.x*blockDim.x + threadIdx.x;
  if(gid >= (long)NB*NPTS) return;
  int b = (int)(gid / NPTS);
  float s0=source[gid*3], s1=source[gid*3+1], s2=source[gid*3+2];
  float* op = out + NB*12 + gid*3;
#pragma unroll
  for(int k=0;k<3;k++){
    float dot = __fmaf_rn(s2, g_Rt[b][k*3+2],
                __fmaf_rn(s1, g_Rt[b][k*3+1],
                __fmul_rn(s0, g_Rt[b][k*3+0])));
    op[k] = __fadd_rn(dot, g_Rt[b][9+k]);
  }
}

extern "C" void kernel_launch(void* const* d_in, const int* in_sizes, int n_in,
                              void* d_out, int out_size){
  (void)in_sizes; (void)n_in; (void)out_size;
  const float* source = (const float*)d_in[0];
  const float* target = (const float*)d_in[1];
  float* out = (float*)d_out;

  cudaFuncSetAttribute(k_bigperm, cudaFuncAttributeMaxDynamicSharedMemorySize, NPTS*8);
  k_bigperm<<<2, 1024, NPTS*8>>>();
  k_tables<<<NIT, 128>>>();
  k_init<<<(NB*SUBN*3 + 255)/256, 256>>>(source, target);
  k_eval<<<NB*NP, SUBN>>>();
  int sb = 0;
  for(int it=0; it<NIT; ++it){
    k_iter<<<NB*NP, SUBN>>>(it, sb);
    sb ^= 1;
  }
  k_final<<<1, 32>>>(sb, out);
  k_align<<<(NB*NPTS + 255)/256, 256>>>(source, out);
}

// round 4
// speedup vs baseline: 1.0465x; 1.0465x over previous
#include <cuda_runtime.h>

typedef unsigned int u32;
typedef unsigned long long u64;

#define NB 32
#define NPTS 16384
#define NP 50
#define SUBN 128
#define NIT 30
#define RRANGE 0.78539816339744830961f

__device__ u32 g_idx[2][SUBN];
__device__ float g_src[NB][SUBN][3];
__device__ float g_tgt[NB][SUBN][3];
__device__ float g_pop[2][NB][NP][6];
__device__ float g_fit[2][NB][NP];
__device__ unsigned char g_perm[NIT][3][NB][NP];
__device__ unsigned char g_mask[NIT][NB][NP];
__device__ float g_Rt[NB][12];
__device__ int g_bar[NB];

__device__ __forceinline__ u32 rotl32(u32 x, u32 r){ return (x<<r)|(x>>(32u-r)); }
__device__ __forceinline__ void tf2x32(u32 k0,u32 k1,u32 x0,u32 x1,u32&o0,u32&o1){
  u32 k2 = k0 ^ k1 ^ 0x1BD11BDAu;
  x0 += k0; x1 += k1;
#define TFR(r) { x0 += x1; x1 = rotl32(x1,(r)); x1 ^= x0; }
  TFR(13) TFR(15) TFR(26) TFR(6)   x0+=k1; x1+=k2+1u;
  TFR(17) TFR(29) TFR(16) TFR(24)  x0+=k2; x1+=k0+2u;
  TFR(13) TFR(15) TFR(26) TFR(6)   x0+=k0; x1+=k1+3u;
  TFR(17) TFR(29) TFR(16) TFR(24)  x0+=k1; x1+=k2+4u;
  TFR(13) TFR(15) TFR(26) TFR(6)   x0+=k2; x1+=k0+5u;
#undef TFR
  o0=x0; o1=x1;
}
struct Key { u32 a, b; };
__device__ __forceinline__ Key split_p(Key k, u32 j){
  Key r; tf2x32(k.a,k.b,0u,j,r.a,r.b); return r;
}
__device__ __forceinline__ u32 rbits_p(Key k, u32 i){
  u32 o0,o1; tf2x32(k.a,k.b,0u,i,o0,o1); return o0^o1;
}
__device__ __forceinline__ float unif01(Key k, u32 i){
  u32 b = rbits_p(k,i);
  return __fsub_rn(__uint_as_float((b>>9)|0x3f800000u), 1.0f);
}

// ---- big permutation: 2-round stable sort-shuffle, one block per array ----
__global__ void k_bigperm(){
  extern __shared__ u64 sh[];
  const int tid = threadIdx.x, nth = blockDim.x;
  Key base; base.a=0u; base.b=42u;
  Key key = split_p(base, blockIdx.x);
  for(int round=0; round<2; round++){
    Key nk  = split_p(key,0);
    Key sub = split_p(key,1);
    key = nk;
    __syncthreads();
    for(int i=tid;i<NPTS;i+=nth){
      u32 pay = (round==0)? (u32)i : (u32)(sh[i] & 0x3FFFull);
      u32 bits = rbits_p(sub,(u32)i);
      sh[i] = ((u64)bits<<32) | ((u64)(u32)i<<14) | (u64)pay;
    }
    for(int k=2;k<=NPTS;k<<=1)
      for(int j=k>>1;j>0;j>>=1){
        __syncthreads();
        for(int p=tid;p<(NPTS>>1);p+=nth){
          int i = ((p & ~(j-1))<<1) | (p & (j-1));
          int l = i + j;
          u64 x = sh[i], y = sh[l];
          if( (x>y) == ((i&k)==0) ){ sh[i]=y; sh[l]=x; }
        }
      }
    __syncthreads();
  }
  for(int i=tid;i<SUBN;i+=nth) g_idx[blockIdx.x][i] = (u32)(sh[i]&0x3FFFull);
}

// ---- per-iteration RNG tables ----
__global__ void k_tables(){
  const int it = blockIdx.x, tid = threadIdx.x;
  Key base; base.a=0u; base.b=42u;
  Key kloop = split_p(base,4);
  Key kit   = split_p(kloop,(u32)it);
  Key ka    = split_p(kit,0);
  Key kb    = split_p(kit,1);
  Key kc    = split_p(kit,2);
  if(tid < 3*NB){
    Key pk  = split_p(ka,(u32)tid);
    Key sub = split_p(pk,1);
    u64 arr[NP];
    for(int i=0;i<NP;i++) arr[i] = ((u64)rbits_p(sub,(u32)i)<<6) | (u64)(u32)i;
    for(int i=1;i<NP;i++){
      u64 v = arr[i]; int j = i-1;
      while(j>=0 && arr[j]>v){ arr[j+1]=arr[j]; j--; }
      arr[j+1]=v;
    }
    int r = tid>>5, b = tid&31;
    for(int i=0;i<NP;i++) g_perm[it][r][b][i] = (unsigned char)(arr[i]&63u);
  }
  Key kr1 = split_p(kc,0);
  Key kr2 = split_p(kc,1);
  for(int f=tid; f<NB*NP; f+=blockDim.x){
    u32 hi = rbits_p(kr1,(u32)f);
    u32 lo = rbits_p(kr2,(u32)f);
    u32 jr = ((hi%6u)*4u + (lo%6u)) % 6u;
    unsigned char m = 0;
    for(int d=0; d<6; d++){
      float u = unif01(kb,(u32)(f*6+d));
      if(u < 0.9f || (u32)d == jr) m |= (unsigned char)(1<<d);
    }
    g_mask[it][f/NP][f%NP] = m;
  }
}

// ---- gather subsets + init population + barrier reset ----
__global__ void k_init(const float* __restrict__ source, const float* __restrict__ target){
  const int gid = blockIdx.x*blockDim.x + threadIdx.x;
  if(gid < NB) g_bar[gid] = 0;
  if(gid < NB*SUBN*3){
    int d = gid%3, i = (gid/3)%SUBN, b = gid/(3*SUBN);
    g_src[b][i][d] = source[((size_t)b*NPTS + g_idx[0][i])*3 + d];
    g_tgt[b][i][d] = target[((size_t)b*NPTS + g_idx[1][i])*3 + d];
  }
  if(gid < NB*NP*3){
    Key base; base.a=0u; base.b=42u;
    Key k2 = split_p(base,2);
    Key k3 = split_p(base,3);
    int d = gid%3, p = (gid/3)%NP, b = gid/(3*NP);
    float r = unif01(k2,(u32)gid);
    float t = unif01(k3,(u32)gid);
    r = fmaxf(-RRANGE, __fadd_rn(__fmul_rn(r, RRANGE+RRANGE), -RRANGE));
    t = fmaxf(-1.0f,   __fadd_rn(__fmul_rn(t, 2.0f), -1.0f));
    if(p==0){ r=0.0f; t=0.0f; }
    g_pop[0][b][p][d]   = r;
    g_pop[0][b][p][d+3] = t;
  }
}

// ---- rotation matrix (identical arithmetic to the passing version) ----
__device__ void compute_R(const float* v, float* R){
  float v0=v[0], v1=v[1], v2=v[2];
  float n2 = __fadd_rn(__fadd_rn(__fmul_rn(v0,v0),__fmul_rn(v1,v1)),__fmul_rn(v2,v2));
  float th = __fsqrt_rn(n2);
  float dn = fmaxf(th, 1e-8f);
  float kx = __fdiv_rn(v0,dn), ky = __fdiv_rn(v1,dn), kz = __fdiv_rn(v2,dn);
  float s = sinf(th), c = cosf(th);
  float omc = __fsub_rn(1.0f, c);
  float K[9] = {0.f,-kz,ky,  kz,0.f,-kx,  -ky,kx,0.f};
#pragma unroll
  for(int i=0;i<3;i++)
#pragma unroll
    for(int j=0;j<3;j++){
      float kk = __fmaf_rn(K[i*3+2],K[2*3+j],
                 __fmaf_rn(K[i*3+1],K[1*3+j],
                 __fmul_rn(K[i*3+0],K[0*3+j])));
      float iden = (i==j)?1.0f:0.0f;
      float r = __fadd_rn(__fadd_rn(iden, __fmul_rn(s,K[i*3+j])), __fmul_rn(omc,kk));
      R[i*3+j] = (th < 1e-8f) ? iden : r;
    }
}

__device__ __forceinline__ float d2f(float x0,float x1,float x2,float xn,
                                     float y0,float y1,float y2,float yn){
  float dot = __fmaf_rn(x2,y2, __fmaf_rn(x1,y1, __fmul_rn(x0,y0)));
  return fmaxf(__fsub_rn(__fadd_rn(xn,yn), __fmul_rn(2.0f,dot)), 0.0f);
}

struct Sh {
  float4 t4[SUBN];
  float4 x4[SUBN];
  float ra[SUBN];
  float ca[SUBN];
  float pose[6];
  int imp;
};

// per-batch software barrier (monotonic counter, reset by k_init each run)
__device__ __forceinline__ void bbar(int b, int n, int target){
  __syncthreads();
  if(n==0){
    __threadfence();
    atomicAdd(&g_bar[b], 1);
    while(atomicAdd(&g_bar[b], 0) < target) __nanosleep(64);
    __threadfence();
  }
  __syncthreads();
}

// fit valid on thread 0
__device__ float eval_pose(Sh& sm, int n,
                           float s0,float s1,float s2,
                           float u0,float u1,float u2,float ynv){
  float R[9];
  compute_R(sm.pose, R);
  float x0 = __fadd_rn(__fmaf_rn(s2,R[2], __fmaf_rn(s1,R[1], __fmul_rn(s0,R[0]))), sm.pose[3]);
  float x1 = __fadd_rn(__fmaf_rn(s2,R[5], __fmaf_rn(s1,R[4], __fmul_rn(s0,R[3]))), sm.pose[4]);
  float x2 = __fadd_rn(__fmaf_rn(s2,R[8], __fmaf_rn(s1,R[7], __fmul_rn(s0,R[6]))), sm.pose[5]);
  float xn = __fadd_rn(__fadd_rn(__fmul_rn(x0,x0),__fmul_rn(x1,x1)),__fmul_rn(x2,x2));
  sm.x4[n] = make_float4(x0,x1,x2,xn);
  __syncthreads();
  const float INF = __int_as_float(0x7f800000);
  float rmin = INF, cmin = INF;
#pragma unroll 8
  for(int m=0;m<SUBN;m++){
    float4 t  = sm.t4[m];
    float4 xx = sm.x4[m];
    rmin = fminf(rmin, d2f(x0,x1,x2,xn, t.x,t.y,t.z,t.w));
    cmin = fminf(cmin, d2f(xx.x,xx.y,xx.z,xx.w, u0,u1,u2,ynv));
  }
  sm.ra[n]=rmin; sm.ca[n]=cmin;
  __syncthreads();
  float fit = 0.0f;
  if(n < 32){
    float pr = __fadd_rn(__fadd_rn(__fadd_rn(sm.ra[n], sm.ra[n+32]), sm.ra[n+64]), sm.ra[n+96]);
    float pc = __fadd_rn(__fadd_rn(__fadd_rn(sm.ca[n], sm.ca[n+32]), sm.ca[n+64]), sm.ca[n+96]);
#pragma unroll
    for(int o=16;o>0;o>>=1){
      pr = __fadd_rn(pr, __shfl_down_sync(0xffffffffu, pr, o));
      pc = __fadd_rn(pc, __shfl_down_sync(0xffffffffu, pc, o));
    }
    fit = __fadd_rn(__fmul_rn(pr,0.0078125f), __fmul_rn(pc,0.0078125f));
  }
  return fit;
}

// ---- persistent DE kernel: init eval + 30 iterations + argmin + align ----
__global__ void __launch_bounds__(SUBN, 12)
k_de(const float* __restrict__ source, float* __restrict__ out){
  __shared__ Sh sm;
  const int b = blockIdx.x / NP, p = blockIdx.x % NP, n = threadIdx.x;

  const float s0=g_src[b][n][0], s1=g_src[b][n][1], s2=g_src[b][n][2];
  const float u0=g_tgt[b][n][0], u1=g_tgt[b][n][1], u2=g_tgt[b][n][2];
  const float ynv = __fadd_rn(__fadd_rn(__fmul_rn(u0,u0),__fmul_rn(u1,u1)),__fmul_rn(u2,u2));
  sm.t4[n] = make_float4(u0,u1,u2,ynv);

  // initial fitness
  if(n<6) sm.pose[n] = g_pop[0][b][p][n];
  __syncthreads();
  float f0 = eval_pose(sm,n,s0,s1,s2,u0,u1,u2,ynv);
  if(n==0) g_fit[0][b][p] = f0;
  bbar(b,n,NP*1);

  int sb = 0;
  for(int it=0; it<NIT; ++it){
    const int db = sb^1;
    if(n<6){
      int r1 = g_perm[it][0][b][p], r2 = g_perm[it][1][b][p], r3 = g_perm[it][2][b][p];
      unsigned char m = g_mask[it][b][p];
      int d = n;
      float mu = __fadd_rn(g_pop[sb][b][r1][d],
                 __fmul_rn(0.8f, __fsub_rn(g_pop[sb][b][r2][d], g_pop[sb][b][r3][d])));
      float lim = (d<3) ? RRANGE : 1.0f;
      mu = fminf(fmaxf(mu, -lim), lim);
      sm.pose[d] = ((m>>d)&1) ? mu : g_pop[sb][b][p][d];
    }
    __syncthreads();
    float tf = eval_pose(sm,n,s0,s1,s2,u0,u1,u2,ynv);
    if(n==0){
      float of = g_fit[sb][b][p];
      sm.imp = (tf < of);
      g_fit[db][b][p] = sm.imp ? tf : of;
    }
    __syncthreads();
    if(n<6) g_pop[db][b][p][n] = sm.imp ? sm.pose[n] : g_pop[sb][b][p][n];
    bbar(b,n,NP*(it+2));
    sb = db;
  }

  // argmin + R/t writeout (block p==0 of each batch)
  if(p==0 && n==0){
    float best = g_fit[sb][b][0]; int bi = 0;
    for(int q=1;q<NP;q++){ float f = g_fit[sb][b][q]; if(f < best){ best=f; bi=q; } }
    float pose[6];
    for(int d=0;d<6;d++) pose[d] = g_pop[sb][b][bi][d];
    float R[9]; compute_R(pose, R);
    for(int i=0;i<9;i++){ out[b*9+i] = R[i]; g_Rt[b][i] = R[i]; }
    for(int k=0;k<3;k++){ out[NB*9 + b*3 + k] = pose[3+k]; g_Rt[b][9+k] = pose[3+k]; }
  }
  bbar(b,n,NP*(NIT+2));

  // aligned output: this batch's 50 blocks cover its 16384 points
  float Rt[12];
#pragma unroll
  for(int i=0;i<12;i++) Rt[i] = g_Rt[b][i];
  const int per = (NPTS + NP - 1)/NP;          // 328
  const int hi  = min((p+1)*per, NPTS);
  for(int i = p*per + n; i < hi; i += SUBN){
    const float* sp = source + ((size_t)b*NPTS + i)*3;
    float a0=sp[0], a1=sp[1], a2=sp[2];
    float* op = out + NB*12 + ((size_t)b*NPTS + i)*3;
#pragma unroll
    for(int k=0;k<3;k++){
      float dot = __fmaf_rn(a2, Rt[k*3+2],
                  __fmaf_rn(a1, Rt[k*3+1],
                  __fmul_rn(a0, Rt[k*3+0])));
      op[k] = __fadd_rn(dot, Rt[9+k]);
    }
  }
}

extern "C" void kernel_launch(void* const* d_in, const int* in_sizes, int n_in,
                              void* d_out, int out_size){
  (void)in_sizes; (void)n_in; (void)out_size;
  const float* source = (const float*)d_in[0];
  const float* target = (const float*)d_in[1];
  float* out = (float*)d_out;

  cudaFuncSetAttribute(k_bigperm, cudaFuncAttributeMaxDynamicSharedMemorySize, NPTS*8);
  k_bigperm<<<2, 1024, NPTS*8>>>();
  k_tables<<<NIT, 128>>>();
  k_init<<<(NB*SUBN*3 + 255)/256, 256>>>(source, target);
  k_de<<<NB*NP, SUBN>>>(source, out);
}

// round 5
// speedup vs baseline: 1.5428x; 1.4743x over previous
#include <cuda_runtime.h>

typedef unsigned int u32;
typedef unsigned long long u64;

#define NB 32
#define NPTS 16384
#define NP 50
#define SUBN 128
#define NIT 30
#define NBUCK 1024
#define RRANGE 0.78539816339744830961f

__device__ u32 g_idx[2][SUBN];
__device__ u32 g_p[2][SUBN];
__device__ float g_src[NB][SUBN][3];
__device__ float g_tgt[NB][SUBN][3];
__device__ float g_pop[2][NB][NP][6];
__device__ float g_fit[2][NB][NP];
__device__ unsigned char g_perm[NIT][3][NB][NP];
__device__ unsigned char g_mask[NIT][NB][NP];
__device__ float g_Rt[NB][12];
__device__ int g_bar[NB];

__device__ __forceinline__ u32 rotl32(u32 x, u32 r){ return (x<<r)|(x>>(32u-r)); }
__device__ __forceinline__ void tf2x32(u32 k0,u32 k1,u32 x0,u32 x1,u32&o0,u32&o1){
  u32 k2 = k0 ^ k1 ^ 0x1BD11BDAu;
  x0 += k0; x1 += k1;
#define TFR(r) { x0 += x1; x1 = rotl32(x1,(r)); x1 ^= x0; }
  TFR(13) TFR(15) TFR(26) TFR(6)   x0+=k1; x1+=k2+1u;
  TFR(17) TFR(29) TFR(16) TFR(24)  x0+=k2; x1+=k0+2u;
  TFR(13) TFR(15) TFR(26) TFR(6)   x0+=k0; x1+=k1+3u;
  TFR(17) TFR(29) TFR(16) TFR(24)  x0+=k1; x1+=k2+4u;
  TFR(13) TFR(15) TFR(26) TFR(6)   x0+=k2; x1+=k0+5u;
#undef TFR
  o0=x0; o1=x1;
}
struct Key { u32 a, b; };
__device__ __forceinline__ Key split_p(Key k, u32 j){
  Key r; tf2x32(k.a,k.b,0u,j,r.a,r.b); return r;
}
__device__ __forceinline__ u32 rbits_p(Key k, u32 i){
  u32 o0,o1; tf2x32(k.a,k.b,0u,i,o0,o1); return o0^o1;
}
__device__ __forceinline__ float unif01(Key k, u32 i){
  u32 b = rbits_p(k,i);
  return __fsub_rn(__uint_as_float((b>>9)|0x3f800000u), 1.0f);
}

// ================= rank-selection replacement for the big sort =================
// final[r] = x1[p_r];  p_r = position of rank-r round-2 key;  x1[p] = element
// with round-1 rank p. Both are exact order-statistic selections with stable
// (bits<<14 | pos) composite ordering.
struct SelSm {
  u32 bits[NPTS];
  u32 list[NPTS];
  u32 hist[NBUCK];
  u32 base[NBUCK+1];
  u32 cursor[NBUCK];
  u32 wsum[32];
  unsigned char needed[NBUCK];
};

__device__ void do_select(SelSm& s, Key sub, const u32* req, u32* out){
  const int t = threadIdx.x, lane = t&31, warp = t>>5;
  for(int i=t;i<NPTS;i+=1024) s.bits[i] = rbits_p(sub,(u32)i);
  s.hist[t] = 0u; s.needed[t] = 0;
  __syncthreads();
  for(int i=t;i<NPTS;i+=1024) atomicAdd(&s.hist[s.bits[i]>>22], 1u);
  __syncthreads();
  u32 orig = s.hist[t]; u32 v = orig;
#pragma unroll
  for(int o=1;o<32;o<<=1){ u32 x=__shfl_up_sync(0xffffffffu,v,o); if(lane>=o) v+=x; }
  if(lane==31) s.wsum[warp]=v;
  __syncthreads();
  if(warp==0){
    u32 w=s.wsum[lane];
#pragma unroll
    for(int o=1;o<32;o<<=1){ u32 x=__shfl_up_sync(0xffffffffu,w,o); if(lane>=o) w+=x; }
    s.wsum[lane]=w;
  }
  __syncthreads();
  u32 incl = v + (warp>0 ? s.wsum[warp-1] : 0u);
  s.base[t+1]=incl; if(t==0) s.base[0]=0u;
  s.cursor[t] = incl - orig;
  __syncthreads();
  if(t<SUBN){
    u32 q = req ? req[t] : (u32)t;
    int lo=0,hi=NBUCK;
    while(hi-lo>1){ int mid=(lo+hi)>>1; if(s.base[mid]<=q) lo=mid; else hi=mid; }
    s.needed[lo]=1;
  }
  __syncthreads();
  for(int i=t;i<NPTS;i+=1024){
    u32 b = s.bits[i]>>22;
    if(s.needed[b]){ u32 pos=atomicAdd(&s.cursor[b],1u); s.list[pos]=(u32)i; }
  }
  __syncthreads();
  if(t<SUBN){
    u32 q = req ? req[t] : (u32)t;
    int lo=0,hi=NBUCK;
    while(hi-lo>1){ int mid=(lo+hi)>>1; if(s.base[mid]<=q) lo=mid; else hi=mid; }
    u32 st=s.base[lo], en=s.base[lo+1], off=q-st;
    u32 ans=0u;
    for(u32 x=st;x<en;x++){
      u32 m=s.list[x]; u64 km=((u64)s.bits[m]<<14)|(u64)m; u32 rk=0;
      for(u32 y=st;y<en;y++){
        u32 o2=s.list[y]; u64 ko=((u64)s.bits[o2]<<14)|(u64)o2;
        rk += (ko<km)?1u:0u;
      }
      if(rk==off){ ans=m; break; }
    }
    out[t]=ans;
  }
}

__global__ void __launch_bounds__(1024,1) k_sel2(){
  extern __shared__ char smraw[];
  SelSm& s = *reinterpret_cast<SelSm*>(smraw);
  const int a = blockIdx.x;
  Key b42; b42.a=0u; b42.b=42u;
  Key ka  = split_p(b42,(u32)a);
  Key kr2 = split_p(ka,0);
  Key sub2= split_p(kr2,1);
  do_select(s, sub2, nullptr, g_p[a]);
}
__global__ void __launch_bounds__(1024,1) k_sel1(){
  extern __shared__ char smraw[];
  SelSm& s = *reinterpret_cast<SelSm*>(smraw);
  const int a = blockIdx.x;
  Key b42; b42.a=0u; b42.b=42u;
  Key ka  = split_p(b42,(u32)a);
  Key sub1= split_p(ka,1);
  do_select(s, sub1, g_p[a], g_idx[a]);
}

// ---- per-iteration RNG tables ----
__global__ void k_tables(){
  const int it = blockIdx.x, tid = threadIdx.x;
  Key base; base.a=0u; base.b=42u;
  Key kloop = split_p(base,4);
  Key kit   = split_p(kloop,(u32)it);
  Key ka    = split_p(kit,0);
  Key kb    = split_p(kit,1);
  Key kc    = split_p(kit,2);
  if(tid < 3*NB){
    Key pk  = split_p(ka,(u32)tid);
    Key sub = split_p(pk,1);
    u64 arr[NP];
    for(int i=0;i<NP;i++) arr[i] = ((u64)rbits_p(sub,(u32)i)<<6) | (u64)(u32)i;
    for(int i=1;i<NP;i++){
      u64 v = arr[i]; int j = i-1;
      while(j>=0 && arr[j]>v){ arr[j+1]=arr[j]; j--; }
      arr[j+1]=v;
    }
    int r = tid>>5, b = tid&31;
    for(int i=0;i<NP;i++) g_perm[it][r][b][i] = (unsigned char)(arr[i]&63u);
  }
  Key kr1 = split_p(kc,0);
  Key kr2 = split_p(kc,1);
  for(int f=tid; f<NB*NP; f+=blockDim.x){
    u32 hi = rbits_p(kr1,(u32)f);
    u32 lo = rbits_p(kr2,(u32)f);
    u32 jr = ((hi%6u)*4u + (lo%6u)) % 6u;
    unsigned char m = 0;
    for(int d=0; d<6; d++){
      float u = unif01(kb,(u32)(f*6+d));
      if(u < 0.9f || (u32)d == jr) m |= (unsigned char)(1<<d);
    }
    g_mask[it][f/NP][f%NP] = m;
  }
}

// ---- gather subsets + init population + barrier reset ----
__global__ void k_init(const float* __restrict__ source, const float* __restrict__ target){
  const int gid = blockIdx.x*blockDim.x + threadIdx.x;
  if(gid < NB) g_bar[gid] = 0;
  if(gid < NB*SUBN*3){
    int d = gid%3, i = (gid/3)%SUBN, b = gid/(3*SUBN);
    g_src[b][i][d] = source[((size_t)b*NPTS + g_idx[0][i])*3 + d];
    g_tgt[b][i][d] = target[((size_t)b*NPTS + g_idx[1][i])*3 + d];
  }
  if(gid < NB*NP*3){
    Key base; base.a=0u; base.b=42u;
    Key k2 = split_p(base,2);
    Key k3 = split_p(base,3);
    int d = gid%3, p = (gid/3)%NP, b = gid/(3*NP);
    float r = unif01(k2,(u32)gid);
    float t = unif01(k3,(u32)gid);
    r = fmaxf(-RRANGE, __fadd_rn(__fmul_rn(r, RRANGE+RRANGE), -RRANGE));
    t = fmaxf(-1.0f,   __fadd_rn(__fmul_rn(t, 2.0f), -1.0f));
    if(p==0){ r=0.0f; t=0.0f; }
    g_pop[0][b][p][d]   = r;
    g_pop[0][b][p][d+3] = t;
  }
}

// ---- rotation matrix (identical arithmetic to the passing version) ----
__device__ void compute_R(const float* v, float* R){
  float v0=v[0], v1=v[1], v2=v[2];
  float n2 = __fadd_rn(__fadd_rn(__fmul_rn(v0,v0),__fmul_rn(v1,v1)),__fmul_rn(v2,v2));
  float th = __fsqrt_rn(n2);
  float dn = fmaxf(th, 1e-8f);
  float kx = __fdiv_rn(v0,dn), ky = __fdiv_rn(v1,dn), kz = __fdiv_rn(v2,dn);
  float s = sinf(th), c = cosf(th);
  float omc = __fsub_rn(1.0f, c);
  float K[9] = {0.f,-kz,ky,  kz,0.f,-kx,  -ky,kx,0.f};
#pragma unroll
  for(int i=0;i<3;i++)
#pragma unroll
    for(int j=0;j<3;j++){
      float kk = __fmaf_rn(K[i*3+2],K[2*3+j],
                 __fmaf_rn(K[i*3+1],K[1*3+j],
                 __fmul_rn(K[i*3+0],K[0*3+j])));
      float iden = (i==j)?1.0f:0.0f;
      float r = __fadd_rn(__fadd_rn(iden, __fmul_rn(s,K[i*3+j])), __fmul_rn(omc,kk));
      R[i*3+j] = (th < 1e-8f) ? iden : r;
    }
}

// d2 with PRE-DOUBLED second operand: dot2 == 2*dot bit-exactly (scaling by 2
// commutes with fp rounding), so fsub(sum, dot2) == fsub(sum, mul(2,dot)).
__device__ __forceinline__ float d2f2(float x0,float x1,float x2,float xn,
                                      float y0d,float y1d,float y2d,float yn){
  float dot2 = __fmaf_rn(x2,y2d, __fmaf_rn(x1,y1d, __fmul_rn(x0,y0d)));
  return fmaxf(__fsub_rn(__fadd_rn(xn,yn), dot2), 0.0f);
}

struct Sh {
  float4 t4[SUBN];   // (2*u0, 2*u1, 2*u2, yn)
  float4 x4[SUBN];   // (x0, x1, x2, xn)
  float ra[SUBN];
  float ca[SUBN];
  float pose[6];
  int imp;
};

__device__ __forceinline__ void bbar(int b, int n, int target){
  __syncthreads();
  if(n==0){
    __threadfence();
    atomicAdd(&g_bar[b], 1);
    while(atomicAdd(&g_bar[b], 0) < target) __nanosleep(64);
    __threadfence();
  }
  __syncthreads();
}

__device__ float eval_pose(Sh& sm, int n,
                           float s0,float s1,float s2,
                           float u0d,float u1d,float u2d,float ynv){
  float R[9];
  compute_R(sm.pose, R);
  float x0 = __fadd_rn(__fmaf_rn(s2,R[2], __fmaf_rn(s1,R[1], __fmul_rn(s0,R[0]))), sm.pose[3]);
  float x1 = __fadd_rn(__fmaf_rn(s2,R[5], __fmaf_rn(s1,R[4], __fmul_rn(s0,R[3]))), sm.pose[4]);
  float x2 = __fadd_rn(__fmaf_rn(s2,R[8], __fmaf_rn(s1,R[7], __fmul_rn(s0,R[6]))), sm.pose[5]);
  float xn = __fadd_rn(__fadd_rn(__fmul_rn(x0,x0),__fmul_rn(x1,x1)),__fmul_rn(x2,x2));
  sm.x4[n] = make_float4(x0,x1,x2,xn);
  __syncthreads();
  const float INF = __int_as_float(0x7f800000);
  float rmin = INF, cmin = INF;
#pragma unroll 8
  for(int m=0;m<SUBN;m++){
    float4 t  = sm.t4[m];   // pre-doubled target
    float4 xx = sm.x4[m];   // unscaled x
    rmin = fminf(rmin, d2f2(x0,x1,x2,xn, t.x,t.y,t.z,t.w));
    cmin = fminf(cmin, d2f2(xx.x,xx.y,xx.z,xx.w, u0d,u1d,u2d,ynv));
  }
  sm.ra[n]=rmin; sm.ca[n]=cmin;
  __syncthreads();
  float fit = 0.0f;
  if(n < 32){
    float pr = __fadd_rn(__fadd_rn(__fadd_rn(sm.ra[n], sm.ra[n+32]), sm.ra[n+64]), sm.ra[n+96]);
    float pc = __fadd_rn(__fadd_rn(__fadd_rn(sm.ca[n], sm.ca[n+32]), sm.ca[n+64]), sm.ca[n+96]);
#pragma unroll
    for(int o=16;o>0;o>>=1){
      pr = __fadd_rn(pr, __shfl_down_sync(0xffffffffu, pr, o));
      pc = __fadd_rn(pc, __shfl_down_sync(0xffffffffu, pc, o));
    }
    fit = __fadd_rn(__fmul_rn(pr,0.0078125f), __fmul_rn(pc,0.0078125f));
  }
  return fit;
}

// ---- persistent DE kernel ----
__global__ void __launch_bounds__(SUBN, 12)
k_de(const float* __restrict__ source, float* __restrict__ out){
  __shared__ Sh sm;
  const int b = blockIdx.x / NP, p = blockIdx.x % NP, n = threadIdx.x;

  const float s0=g_src[b][n][0], s1=g_src[b][n][1], s2=g_src[b][n][2];
  const float u0=g_tgt[b][n][0], u1=g_tgt[b][n][1], u2=g_tgt[b][n][2];
  const float ynv = __fadd_rn(__fadd_rn(__fmul_rn(u0,u0),__fmul_rn(u1,u1)),__fmul_rn(u2,u2));
  const float u0d=__fadd_rn(u0,u0), u1d=__fadd_rn(u1,u1), u2d=__fadd_rn(u2,u2); // exact 2x
  sm.t4[n] = make_float4(u0d,u1d,u2d,ynv);

  if(n<6) sm.pose[n] = g_pop[0][b][p][n];
  __syncthreads();
  float f0 = eval_pose(sm,n,s0,s1,s2,u0d,u1d,u2d,ynv);
  if(n==0) g_fit[0][b][p] = f0;
  bbar(b,n,NP*1);

  int sb = 0;
  for(int it=0; it<NIT; ++it){
    const int db = sb^1;
    if(n<6){
      int r1 = g_perm[it][0][b][p], r2 = g_perm[it][1][b][p], r3 = g_perm[it][2][b][p];
      unsigned char m = g_mask[it][b][p];
      int d = n;
      float mu = __fadd_rn(g_pop[sb][b][r1][d],
                 __fmul_rn(0.8f, __fsub_rn(g_pop[sb][b][r2][d], g_pop[sb][b][r3][d])));
      float lim = (d<3) ? RRANGE : 1.0f;
      mu = fminf(fmaxf(mu, -lim), lim);
      sm.pose[d] = ((m>>d)&1) ? mu : g_pop[sb][b][p][d];
    }
    __syncthreads();
    float tf = eval_pose(sm,n,s0,s1,s2,u0d,u1d,u2d,ynv);
    if(n==0){
      float of = g_fit[sb][b][p];
      sm.imp = (tf < of);
      g_fit[db][b][p] = sm.imp ? tf : of;
    }
    __syncthreads();
    if(n<6) g_pop[db][b][p][n] = sm.imp ? sm.pose[n] : g_pop[sb][b][p][n];
    bbar(b,n,NP*(it+2));
    sb = db;
  }

  if(p==0 && n==0){
    float best = g_fit[sb][b][0]; int bi = 0;
    for(int q=1;q<NP;q++){ float f = g_fit[sb][b][q]; if(f < best){ best=f; bi=q; } }
    float pose[6];
    for(int d=0;d<6;d++) pose[d] = g_pop[sb][b][bi][d];
    float R[9]; compute_R(pose, R);
    for(int i=0;i<9;i++){ out[b*9+i] = R[i]; g_Rt[b][i] = R[i]; }
    for(int k=0;k<3;k++){ out[NB*9 + b*3 + k] = pose[3+k]; g_Rt[b][9+k] = pose[3+k]; }
  }
  bbar(b,n,NP*(NIT+2));

  float Rt[12];
#pragma unroll
  for(int i=0;i<12;i++) Rt[i] = g_Rt[b][i];
  const int per = (NPTS + NP - 1)/NP;
  const int hi  = min((p+1)*per, NPTS);
  for(int i = p*per + n; i < hi; i += SUBN){
    const float* sp = source + ((size_t)b*NPTS + i)*3;
    float a0=sp[0], a1=sp[1], a2=sp[2];
    float* op = out + NB*12 + ((size_t)b*NPTS + i)*3;
#pragma unroll
    for(int k=0;k<3;k++){
      float dot = __fmaf_rn(a2, Rt[k*3+2],
                  __fmaf_rn(a1, Rt[k*3+1],
                  __fmul_rn(a0, Rt[k*3+0])));
      op[k] = __fadd_rn(dot, Rt[9+k]);
    }
  }
}

extern "C" void kernel_launch(void* const* d_in, const int* in_sizes, int n_in,
                              void* d_out, int out_size){
  (void)in_sizes; (void)n_in; (void)out_size;
  const float* source = (const float*)d_in[0];
  const float* target = (const float*)d_in[1];
  float* out = (float*)d_out;

  cudaFuncSetAttribute(k_sel2, cudaFuncAttributeMaxDynamicSharedMemorySize, (int)sizeof(SelSm));
  cudaFuncSetAttribute(k_sel1, cudaFuncAttributeMaxDynamicSharedMemorySize, (int)sizeof(SelSm));
  k_sel2<<<2, 1024, sizeof(SelSm)>>>();
  k_sel1<<<2, 1024, sizeof(SelSm)>>>();
  k_tables<<<NIT, 128>>>();
  k_init<<<(NB*SUBN*3 + 255)/256, 256>>>(source, target);
  k_de<<<NB*NP, SUBN>>>(source, out);
}

// round 6
// speedup vs baseline: 1.7833x; 1.1558x over previous
#include <cuda_runtime.h>

typedef unsigned int u32;
typedef unsigned long long u64;

#define NB 32
#define NPTS 16384
#define NP 50
#define SUBN 128
#define NIT 30
#define NBUCK 1024
#define BPB 25                    // blocks per batch (2 particles each)
#define RRANGE 0.78539816339744830961f

__device__ u32 g_idx[2][SUBN];
__device__ u32 g_p[2][SUBN];
__device__ float g_src[NB][SUBN][3];
__device__ float g_tgt[NB][SUBN][3];
__device__ float g_pop[2][NB][NP][6];
__device__ float g_fit[2][NB][NP];
__device__ unsigned char g_perm[NIT][3][NB][NP];
__device__ unsigned char g_mask[NIT][NB][NP];
__device__ float g_Rt[NB][12];
__device__ int g_bar[NB];

__device__ __forceinline__ u32 rotl32(u32 x, u32 r){ return (x<<r)|(x>>(32u-r)); }
__device__ __forceinline__ void tf2x32(u32 k0,u32 k1,u32 x0,u32 x1,u32&o0,u32&o1){
  u32 k2 = k0 ^ k1 ^ 0x1BD11BDAu;
  x0 += k0; x1 += k1;
#define TFR(r) { x0 += x1; x1 = rotl32(x1,(r)); x1 ^= x0; }
  TFR(13) TFR(15) TFR(26) TFR(6)   x0+=k1; x1+=k2+1u;
  TFR(17) TFR(29) TFR(16) TFR(24)  x0+=k2; x1+=k0+2u;
  TFR(13) TFR(15) TFR(26) TFR(6)   x0+=k0; x1+=k1+3u;
  TFR(17) TFR(29) TFR(16) TFR(24)  x0+=k1; x1+=k2+4u;
  TFR(13) TFR(15) TFR(26) TFR(6)   x0+=k2; x1+=k0+5u;
#undef TFR
  o0=x0; o1=x1;
}
struct Key { u32 a, b; };
__device__ __forceinline__ Key split_p(Key k, u32 j){
  Key r; tf2x32(k.a,k.b,0u,j,r.a,r.b); return r;
}
__device__ __forceinline__ u32 rbits_p(Key k, u32 i){
  u32 o0,o1; tf2x32(k.a,k.b,0u,i,o0,o1); return o0^o1;
}
__device__ __forceinline__ float unif01(Key k, u32 i){
  u32 b = rbits_p(k,i);
  return __fsub_rn(__uint_as_float((b>>9)|0x3f800000u), 1.0f);
}

// ---- packed f32x2 helpers (IEEE rn per lane; bit-identical to scalar) ----
__device__ __forceinline__ u64 pack2(float lo, float hi){
  u64 v; asm("mov.b64 %0, {%1,%2};" : "=l"(v)
             : "r"(__float_as_uint(lo)), "r"(__float_as_uint(hi))); return v;
}
__device__ __forceinline__ void unpack2(u64 v, float& lo, float& hi){
  u32 a,b; asm("mov.b64 {%0,%1}, %2;" : "=r"(a),"=r"(b) : "l"(v));
  lo=__uint_as_float(a); hi=__uint_as_float(b);
}
__device__ __forceinline__ u64 mul2(u64 a, u64 b){
  u64 d; asm("mul.rn.f32x2 %0,%1,%2;" : "=l"(d) : "l"(a),"l"(b)); return d; }
__device__ __forceinline__ u64 add2(u64 a, u64 b){
  u64 d; asm("add.rn.f32x2 %0,%1,%2;" : "=l"(d) : "l"(a),"l"(b)); return d; }
__device__ __forceinline__ u64 fma2_(u64 a, u64 b, u64 c){
  u64 d; asm("fma.rn.f32x2 %0,%1,%2,%3;" : "=l"(d) : "l"(a),"l"(b),"l"(c)); return d; }

// ================= rank selection (exact, replaces bitonic sort) =================
struct SelSm {
  u32 bits[NPTS];
  u32 list[NPTS];
  u32 hist[NBUCK];
  u32 base[NBUCK+1];
  u32 cursor[NBUCK];
  u32 wsum[32];
  unsigned char needed[NBUCK];
};

__device__ void do_select(SelSm& s, Key sub, const u32* req, u32* out){
  const int t = threadIdx.x, lane = t&31, warp = t>>5;
  for(int i=t;i<NPTS;i+=1024) s.bits[i] = rbits_p(sub,(u32)i);
  s.hist[t] = 0u; s.needed[t] = 0;
  __syncthreads();
  for(int i=t;i<NPTS;i+=1024) atomicAdd(&s.hist[s.bits[i]>>22], 1u);
  __syncthreads();
  u32 orig = s.hist[t]; u32 v = orig;
#pragma unroll
  for(int o=1;o<32;o<<=1){ u32 x=__shfl_up_sync(0xffffffffu,v,o); if(lane>=o) v+=x; }
  if(lane==31) s.wsum[warp]=v;
  __syncthreads();
  if(warp==0){
    u32 w=s.wsum[lane];
#pragma unroll
    for(int o=1;o<32;o<<=1){ u32 x=__shfl_up_sync(0xffffffffu,w,o); if(lane>=o) w+=x; }
    s.wsum[lane]=w;
  }
  __syncthreads();
  u32 incl = v + (warp>0 ? s.wsum[warp-1] : 0u);
  s.base[t+1]=incl; if(t==0) s.base[0]=0u;
  s.cursor[t] = incl - orig;
  __syncthreads();
  if(t<SUBN){
    u32 q = req ? req[t] : (u32)t;
    int lo=0,hi=NBUCK;
    while(hi-lo>1){ int mid=(lo+hi)>>1; if(s.base[mid]<=q) lo=mid; else hi=mid; }
    s.needed[lo]=1;
  }
  __syncthreads();
  for(int i=t;i<NPTS;i+=1024){
    u32 b = s.bits[i]>>22;
    if(s.needed[b]){ u32 pos=atomicAdd(&s.cursor[b],1u); s.list[pos]=(u32)i; }
  }
  __syncthreads();
  if(t<SUBN){
    u32 q = req ? req[t] : (u32)t;
    int lo=0,hi=NBUCK;
    while(hi-lo>1){ int mid=(lo+hi)>>1; if(s.base[mid]<=q) lo=mid; else hi=mid; }
    u32 st=s.base[lo], en=s.base[lo+1], off=q-st;
    u32 ans=0u;
    for(u32 x=st;x<en;x++){
      u32 m=s.list[x]; u64 km=((u64)s.bits[m]<<14)|(u64)m; u32 rk=0;
      for(u32 y=st;y<en;y++){
        u32 o2=s.list[y]; u64 ko=((u64)s.bits[o2]<<14)|(u64)o2;
        rk += (ko<km)?1u:0u;
      }
      if(rk==off){ ans=m; break; }
    }
    out[t]=ans;
  }
}

__global__ void __launch_bounds__(1024,1) k_sel2(){
  extern __shared__ char smraw[];
  SelSm& s = *reinterpret_cast<SelSm*>(smraw);
  const int a = blockIdx.x;
  Key b42; b42.a=0u; b42.b=42u;
  Key ka  = split_p(b42,(u32)a);
  Key kr2 = split_p(ka,0);
  Key sub2= split_p(kr2,1);
  do_select(s, sub2, nullptr, g_p[a]);
}
__global__ void __launch_bounds__(1024,1) k_sel1(){
  extern __shared__ char smraw[];
  SelSm& s = *reinterpret_cast<SelSm*>(smraw);
  const int a = blockIdx.x;
  Key b42; b42.a=0u; b42.b=42u;
  Key ka  = split_p(b42,(u32)a);
  Key sub1= split_p(ka,1);
  do_select(s, sub1, g_p[a], g_idx[a]);
}

// ---- per-iteration RNG tables ----
__global__ void k_tables(){
  const int it = blockIdx.x, tid = threadIdx.x;
  Key base; base.a=0u; base.b=42u;
  Key kloop = split_p(base,4);
  Key kit   = split_p(kloop,(u32)it);
  Key ka    = split_p(kit,0);
  Key kb    = split_p(kit,1);
  Key kc    = split_p(kit,2);
  if(tid < 3*NB){
    Key pk  = split_p(ka,(u32)tid);
    Key sub = split_p(pk,1);
    u64 arr[NP];
    for(int i=0;i<NP;i++) arr[i] = ((u64)rbits_p(sub,(u32)i)<<6) | (u64)(u32)i;
    for(int i=1;i<NP;i++){
      u64 v = arr[i]; int j = i-1;
      while(j>=0 && arr[j]>v){ arr[j+1]=arr[j]; j--; }
      arr[j+1]=v;
    }
    int r = tid>>5, b = tid&31;
    for(int i=0;i<NP;i++) g_perm[it][r][b][i] = (unsigned char)(arr[i]&63u);
  }
  Key kr1 = split_p(kc,0);
  Key kr2 = split_p(kc,1);
  for(int f=tid; f<NB*NP; f+=blockDim.x){
    u32 hi = rbits_p(kr1,(u32)f);
    u32 lo = rbits_p(kr2,(u32)f);
    u32 jr = ((hi%6u)*4u + (lo%6u)) % 6u;
    unsigned char m = 0;
    for(int d=0; d<6; d++){
      float u = unif01(kb,(u32)(f*6+d));
      if(u < 0.9f || (u32)d == jr) m |= (unsigned char)(1<<d);
    }
    g_mask[it][f/NP][f%NP] = m;
  }
}

// ---- gather subsets + init population + barrier reset ----
__global__ void k_init(const float* __restrict__ source, const float* __restrict__ target){
  const int gid = blockIdx.x*blockDim.x + threadIdx.x;
  if(gid < NB) g_bar[gid] = 0;
  if(gid < NB*SUBN*3){
    int d = gid%3, i = (gid/3)%SUBN, b = gid/(3*SUBN);
    g_src[b][i][d] = source[((size_t)b*NPTS + g_idx[0][i])*3 + d];
    g_tgt[b][i][d] = target[((size_t)b*NPTS + g_idx[1][i])*3 + d];
  }
  if(gid < NB*NP*3){
    Key base; base.a=0u; base.b=42u;
    Key k2 = split_p(base,2);
    Key k3 = split_p(base,3);
    int d = gid%3, p = (gid/3)%NP, b = gid/(3*NP);
    float r = unif01(k2,(u32)gid);
    float t = unif01(k3,(u32)gid);
    r = fmaxf(-RRANGE, __fadd_rn(__fmul_rn(r, RRANGE+RRANGE), -RRANGE));
    t = fmaxf(-1.0f,   __fadd_rn(__fmul_rn(t, 2.0f), -1.0f));
    if(p==0){ r=0.0f; t=0.0f; }
    g_pop[0][b][p][d]   = r;
    g_pop[0][b][p][d+3] = t;
  }
}

// ---- rotation matrix (identical arithmetic to passing version) ----
__device__ void compute_R(const float* v, float* R){
  float v0=v[0], v1=v[1], v2=v[2];
  float n2 = __fadd_rn(__fadd_rn(__fmul_rn(v0,v0),__fmul_rn(v1,v1)),__fmul_rn(v2,v2));
  float th = __fsqrt_rn(n2);
  float dn = fmaxf(th, 1e-8f);
  float kx = __fdiv_rn(v0,dn), ky = __fdiv_rn(v1,dn), kz = __fdiv_rn(v2,dn);
  float s = sinf(th), c = cosf(th);
  float omc = __fsub_rn(1.0f, c);
  float K[9] = {0.f,-kz,ky,  kz,0.f,-kx,  -ky,kx,0.f};
#pragma unroll
  for(int i=0;i<3;i++)
#pragma unroll
    for(int j=0;j<3;j++){
      float kk = __fmaf_rn(K[i*3+2],K[2*3+j],
                 __fmaf_rn(K[i*3+1],K[1*3+j],
                 __fmul_rn(K[i*3+0],K[0*3+j])));
      float iden = (i==j)?1.0f:0.0f;
      float r = __fadd_rn(__fadd_rn(iden, __fmul_rn(s,K[i*3+j])), __fmul_rn(omc,kk));
      R[i*3+j] = (th < 1e-8f) ? iden : r;
    }
}

// Pair-interleaved shared tiles: one LDS.128 = two packed b64 operands.
struct Sh {
  ulonglong2 tA[SUBN/2];   // (t0d[m],t0d[m+1] | t1d[m],t1d[m+1])
  ulonglong2 tB[SUBN/2];   // (t2d[m],t2d[m+1] | yn[m],  yn[m+1])
  ulonglong2 xA[SUBN/2];   // (x0 pair | x1 pair)
  ulonglong2 xB[SUBN/2];   // (x2 pair | xn pair)
  float ra[SUBN];
  float ca[SUBN];
  float pose[12];          // two poses
  int imp[2];
};

__device__ __forceinline__ void bbar(int b, int n, int target){
  __syncthreads();
  if(n==0){
    __threadfence();
    atomicAdd(&g_bar[b], 1);
    while(atomicAdd(&g_bar[b], 0) < target) __nanosleep(64);
    __threadfence();
  }
  __syncthreads();
}

// fit valid on thread 0
__device__ float eval_pose(Sh& sm, int n, const float* pose,
                           float s0,float s1,float s2,
                           u64 nu0,u64 nu1,u64 nu2,u64 ynb){
  float R[9];
  compute_R(pose, R);
  float x0 = __fadd_rn(__fmaf_rn(s2,R[2], __fmaf_rn(s1,R[1], __fmul_rn(s0,R[0]))), pose[3]);
  float x1 = __fadd_rn(__fmaf_rn(s2,R[5], __fmaf_rn(s1,R[4], __fmul_rn(s0,R[3]))), pose[4]);
  float x2 = __fadd_rn(__fmaf_rn(s2,R[8], __fmaf_rn(s1,R[7], __fmul_rn(s0,R[6]))), pose[5]);
  float xn = __fadd_rn(__fadd_rn(__fmul_rn(x0,x0),__fmul_rn(x1,x1)),__fmul_rn(x2,x2));
  {
    int mp = n>>1, h = n&1;
    float* pA = (float*)&sm.xA[mp];
    float* pB = (float*)&sm.xB[mp];
    pA[h] = x0; pA[2+h] = x1;
    pB[h] = x2; pB[2+h] = xn;
  }
  // broadcasts for rmin direction: negated x (exact), duplicated xn
  u64 nx0 = pack2(-x0,-x0), nx1 = pack2(-x1,-x1), nx2 = pack2(-x2,-x2);
  u64 xnb = pack2(xn,xn);
  __syncthreads();
  const float INF = __int_as_float(0x7f800000);
  float r0=INF,r1=INF,c0=INF,c1=INF;
#pragma unroll 4
  for(int mp=0;mp<SUBN/2;mp++){
    ulonglong2 a  = sm.tA[mp];
    ulonglong2 bb = sm.tB[mp];
    // -dot2 = fma(-x2,t2d, fma(-x1,t1d, (-x0)*t0d))  (== -(dot2) bit-exactly)
    u64 nd = fma2_(nx2, bb.x, fma2_(nx1, a.y, mul2(nx0, a.x)));
    u64 dd = add2(add2(xnb, bb.y), nd);     // fadd(xn,yn) + (-dot2) == fsub(sum,dot2)
    float dl,dh; unpack2(dd,dl,dh);
    r0 = fminf(r0,dl); r1 = fminf(r1,dh);
    ulonglong2 xa = sm.xA[mp];
    ulonglong2 xb = sm.xB[mp];
    u64 nd2 = fma2_(nu2, xb.x, fma2_(nu1, xa.y, mul2(nu0, xa.x)));
    u64 dd2 = add2(add2(ynb, xb.y), nd2);
    unpack2(dd2,dl,dh);
    c0 = fminf(c0,dl); c1 = fminf(c1,dh);
  }
  // clamp hoisted out of loop: min_m max(d,0) == max(min_m d, 0)
  float rmin = fmaxf(fminf(r0,r1), 0.0f);
  float cmin = fmaxf(fminf(c0,c1), 0.0f);
  sm.ra[n]=rmin; sm.ca[n]=cmin;
  __syncthreads();
  float fit = 0.0f;
  if(n < 32){
    float pr = __fadd_rn(__fadd_rn(__fadd_rn(sm.ra[n], sm.ra[n+32]), sm.ra[n+64]), sm.ra[n+96]);
    float pc = __fadd_rn(__fadd_rn(__fadd_rn(sm.ca[n], sm.ca[n+32]), sm.ca[n+64]), sm.ca[n+96]);
#pragma unroll
    for(int o=16;o>0;o>>=1){
      pr = __fadd_rn(pr, __shfl_down_sync(0xffffffffu, pr, o));
      pc = __fadd_rn(pc, __shfl_down_sync(0xffffffffu, pc, o));
    }
    fit = __fadd_rn(__fmul_rn(pr,0.0078125f), __fmul_rn(pc,0.0078125f));
  }
  __syncthreads();
  return fit;
}

// ---- persistent DE kernel: 2 particles per block ----
__global__ void __launch_bounds__(SUBN, 7)
k_de(const float* __restrict__ source, float* __restrict__ out){
  __shared__ Sh sm;
  const int b = blockIdx.x / BPB, q = blockIdx.x % BPB, n = threadIdx.x;
  const int p0 = 2*q, p1 = 2*q+1;

  const float s0=g_src[b][n][0], s1=g_src[b][n][1], s2=g_src[b][n][2];
  const float u0=g_tgt[b][n][0], u1=g_tgt[b][n][1], u2=g_tgt[b][n][2];
  const float ynv = __fadd_rn(__fadd_rn(__fmul_rn(u0,u0),__fmul_rn(u1,u1)),__fmul_rn(u2,u2));
  const float u0d=__fadd_rn(u0,u0), u1d=__fadd_rn(u1,u1), u2d=__fadd_rn(u2,u2);
  {
    int mp = n>>1, h = n&1;
    float* pA = (float*)&sm.tA[mp];
    float* pB = (float*)&sm.tB[mp];
    pA[h] = u0d; pA[2+h] = u1d;
    pB[h] = u2d; pB[2+h] = ynv;
  }
  // persistent cmin-direction broadcasts: negated doubled target of THIS thread
  const u64 nu0 = pack2(-u0d,-u0d), nu1 = pack2(-u1d,-u1d), nu2 = pack2(-u2d,-u2d);
  const u64 ynb = pack2(ynv,ynv);

  if(n<12) sm.pose[n] = g_pop[0][b][p0 + n/6][n%6];
  __syncthreads();
  float f = eval_pose(sm,n,sm.pose+0,s0,s1,s2,nu0,nu1,nu2,ynb);
  if(n==0) g_fit[0][b][p0] = f;
  f = eval_pose(sm,n,sm.pose+6,s0,s1,s2,nu0,nu1,nu2,ynb);
  if(n==0) g_fit[0][b][p1] = f;
  bbar(b,n,BPB*1);

  int sb = 0;
  for(int it=0; it<NIT; ++it){
    const int db = sb^1;
    if(n<12){
      const int pp = n/6, d = n%6, p = p0 + pp;
      int r1 = g_perm[it][0][b][p], r2 = g_perm[it][1][b][p], r3 = g_perm[it][2][b][p];
      unsigned char m = g_mask[it][b][p];
      float mu = __fadd_rn(g_pop[sb][b][r1][d],
                 __fmul_rn(0.8f, __fsub_rn(g_pop[sb][b][r2][d], g_pop[sb][b][r3][d])));
      float lim = (d<3) ? RRANGE : 1.0f;
      mu = fminf(fmaxf(mu, -lim), lim);
      sm.pose[n] = ((m>>d)&1) ? mu : g_pop[sb][b][p][d];
    }
    __syncthreads();
    float tf0 = eval_pose(sm,n,sm.pose+0,s0,s1,s2,nu0,nu1,nu2,ynb);
    float tf1 = eval_pose(sm,n,sm.pose+6,s0,s1,s2,nu0,nu1,nu2,ynb);
    if(n==0){
      float of0 = g_fit[sb][b][p0], of1 = g_fit[sb][b][p1];
      sm.imp[0] = (tf0 < of0);
      sm.imp[1] = (tf1 < of1);
      g_fit[db][b][p0] = sm.imp[0] ? tf0 : of0;
      g_fit[db][b][p1] = sm.imp[1] ? tf1 : of1;
    }
    __syncthreads();
    if(n<12){
      const int pp = n/6, d = n%6, p = p0 + pp;
      g_pop[db][b][p][d] = sm.imp[pp] ? sm.pose[n] : g_pop[sb][b][p][d];
    }
    bbar(b,n,BPB*(it+2));
    sb = db;
  }

  if(q==0 && n==0){
    float best = g_fit[sb][b][0]; int bi = 0;
    for(int pq=1;pq<NP;pq++){ float ff = g_fit[sb][b][pq]; if(ff < best){ best=ff; bi=pq; } }
    float pose[6];
    for(int d=0;d<6;d++) pose[d] = g_pop[sb][b][bi][d];
    float R[9]; compute_R(pose, R);
    for(int i=0;i<9;i++){ out[b*9+i] = R[i]; g_Rt[b][i] = R[i]; }
    for(int k=0;k<3;k++){ out[NB*9 + b*3 + k] = pose[3+k]; g_Rt[b][9+k] = pose[3+k]; }
  }
  bbar(b,n,BPB*(NIT+2));

  float Rt[12];
#pragma unroll
  for(int i=0;i<12;i++) Rt[i] = g_Rt[b][i];
  const int per = (NPTS + BPB - 1)/BPB;            // 656
  const int hi  = min((q+1)*per, NPTS);
  for(int i = q*per + n; i < hi; i += SUBN){
    const float* sp = source + ((size_t)b*NPTS + i)*3;
    float a0=sp[0], a1=sp[1], a2=sp[2];
    float* op = out + NB*12 + ((size_t)b*NPTS + i)*3;
#pragma unroll
    for(int k=0;k<3;k++){
      float dot = __fmaf_rn(a2, Rt[k*3+2],
                  __fmaf_rn(a1, Rt[k*3+1],
                  __fmul_rn(a0, Rt[k*3+0])));
      op[k] = __fadd_rn(dot, Rt[9+k]);
    }
  }
}

extern "C" void kernel_launch(void* const* d_in, const int* in_sizes, int n_in,
                              void* d_out, int out_size){
  (void)in_sizes; (void)n_in; (void)out_size;
  const float* source = (const float*)d_in[0];
  const float* target = (const float*)d_in[1];
  float* out = (float*)d_out;

  cudaFuncSetAttribute(k_sel2, cudaFuncAttributeMaxDynamicSharedMemorySize, (int)sizeof(SelSm));
  cudaFuncSetAttribute(k_sel1, cudaFuncAttributeMaxDynamicSharedMemorySize, (int)sizeof(SelSm));
  k_sel2<<<2, 1024, sizeof(SelSm)>>>();
  k_sel1<<<2, 1024, sizeof(SelSm)>>>();
  k_tables<<<NIT, 128>>>();
  k_init<<<(NB*SUBN*3 + 255)/256, 256>>>(source, target);
  k_de<<<NB*BPB, SUBN>>>(source, out);
}

// round 8
// speedup vs baseline: 1.8770x; 1.0526x over previous
#include <cuda_runtime.h>

typedef unsigned int u32;
typedef unsigned long long u64;

#define NB 32
#define NPTS 16384
#define NP 50
#define SUBN 128
#define NIT 30
#define NBUCK 1024
#define BPB 25
#define RRANGE 0.78539816339744830961f

__device__ u32 g_idx[2][SUBN];
__device__ u32 g_p[2][SUBN];
__device__ float g_src[NB][SUBN][3];
__device__ float g_tgt[NB][SUBN][3];
__device__ float g_pop[2][NB][NP][6];
__device__ float g_fit[2][NB][NP];
__device__ unsigned char g_perm[NIT][3][NB][NP];
__device__ unsigned char g_mask[NIT][NB][NP];
__device__ float g_Rt[NB][12];
__device__ int g_bar[NB];

__device__ __forceinline__ u32 rotl32(u32 x, u32 r){ return (x<<r)|(x>>(32u-r)); }
__device__ __forceinline__ void tf2x32(u32 k0,u32 k1,u32 x0,u32 x1,u32&o0,u32&o1){
  u32 k2 = k0 ^ k1 ^ 0x1BD11BDAu;
  x0 += k0; x1 += k1;
#define TFR(r) { x0 += x1; x1 = rotl32(x1,(r)); x1 ^= x0; }
  TFR(13) TFR(15) TFR(26) TFR(6)   x0+=k1; x1+=k2+1u;
  TFR(17) TFR(29) TFR(16) TFR(24)  x0+=k2; x1+=k0+2u;
  TFR(13) TFR(15) TFR(26) TFR(6)   x0+=k0; x1+=k1+3u;
  TFR(17) TFR(29) TFR(16) TFR(24)  x0+=k1; x1+=k2+4u;
  TFR(13) TFR(15) TFR(26) TFR(6)   x0+=k2; x1+=k0+5u;
#undef TFR
  o0=x0; o1=x1;
}
struct Key { u32 a, b; };
__device__ __forceinline__ Key split_p(Key k, u32 j){
  Key r; tf2x32(k.a,k.b,0u,j,r.a,r.b); return r;
}
__device__ __forceinline__ u32 rbits_p(Key k, u32 i){
  u32 o0,o1; tf2x32(k.a,k.b,0u,i,o0,o1); return o0^o1;
}
__device__ __forceinline__ float unif01(Key k, u32 i){
  u32 b = rbits_p(k,i);
  return __fsub_rn(__uint_as_float((b>>9)|0x3f800000u), 1.0f);
}

// ---- packed f32x2 helpers (IEEE rn per lane; bit-identical to scalar) ----
__device__ __forceinline__ u64 pack2(float lo, float hi){
  u64 v; asm("mov.b64 %0, {%1,%2};" : "=l"(v)
             : "r"(__float_as_uint(lo)), "r"(__float_as_uint(hi))); return v;
}
__device__ __forceinline__ void unpack2(u64 v, float& lo, float& hi){
  u32 a,b; asm("mov.b64 {%0,%1}, %2;" : "=r"(a),"=r"(b) : "l"(v));
  lo=__uint_as_float(a); hi=__uint_as_float(b);
}
__device__ __forceinline__ u64 mul2(u64 a, u64 b){
  u64 d; asm("mul.rn.f32x2 %0,%1,%2;" : "=l"(d) : "l"(a),"l"(b)); return d; }
__device__ __forceinline__ u64 add2(u64 a, u64 b){
  u64 d; asm("add.rn.f32x2 %0,%1,%2;" : "=l"(d) : "l"(a),"l"(b)); return d; }
__device__ __forceinline__ u64 fma2_(u64 a, u64 b, u64 c){
  u64 d; asm("fma.rn.f32x2 %0,%1,%2,%3;" : "=l"(d) : "l"(a),"l"(b),"l"(c)); return d; }

// ================= rank selection (exact, replaces bitonic sort) =================
struct SelSm {
  u32 bits[NPTS];
  u32 list[NPTS];
  u32 hist[NBUCK];
  u32 base[NBUCK+1];
  u32 cursor[NBUCK];
  u32 wsum[32];
  unsigned char needed[NBUCK];
};

__device__ void do_select(SelSm& s, Key sub, const u32* req, u32* out){
  const int t = threadIdx.x, lane = t&31, warp = t>>5;
  for(int i=t;i<NPTS;i+=1024) s.bits[i] = rbits_p(sub,(u32)i);
  s.hist[t] = 0u; s.needed[t] = 0;
  __syncthreads();
  for(int i=t;i<NPTS;i+=1024) atomicAdd(&s.hist[s.bits[i]>>22], 1u);
  __syncthreads();
  u32 orig = s.hist[t]; u32 v = orig;
#pragma unroll
  for(int o=1;o<32;o<<=1){ u32 x=__shfl_up_sync(0xffffffffu,v,o); if(lane>=o) v+=x; }
  if(lane==31) s.wsum[warp]=v;
  __syncthreads();
  if(warp==0){
    u32 w=s.wsum[lane];
#pragma unroll
    for(int o=1;o<32;o<<=1){ u32 x=__shfl_up_sync(0xffffffffu,w,o); if(lane>=o) w+=x; }
    s.wsum[lane]=w;
  }
  __syncthreads();
  u32 incl = v + (warp>0 ? s.wsum[warp-1] : 0u);
  s.base[t+1]=incl; if(t==0) s.base[0]=0u;
  s.cursor[t] = incl - orig;
  __syncthreads();
  if(t<SUBN){
    u32 q = req ? req[t] : (u32)t;
    int lo=0,hi=NBUCK;
    while(hi-lo>1){ int mid=(lo+hi)>>1; if(s.base[mid]<=q) lo=mid; else hi=mid; }
    s.needed[lo]=1;
  }
  __syncthreads();
  for(int i=t;i<NPTS;i+=1024){
    u32 b = s.bits[i]>>22;
    if(s.needed[b]){ u32 pos=atomicAdd(&s.cursor[b],1u); s.list[pos]=(u32)i; }
  }
  __syncthreads();
  if(t<SUBN){
    u32 q = req ? req[t] : (u32)t;
    int lo=0,hi=NBUCK;
    while(hi-lo>1){ int mid=(lo+hi)>>1; if(s.base[mid]<=q) lo=mid; else hi=mid; }
    u32 st=s.base[lo], en=s.base[lo+1], off=q-st;
    u32 ans=0u;
    for(u32 x=st;x<en;x++){
      u32 m=s.list[x]; u64 km=((u64)s.bits[m]<<14)|(u64)m; u32 rk=0;
      for(u32 y=st;y<en;y++){
        u32 o2=s.list[y]; u64 ko=((u64)s.bits[o2]<<14)|(u64)o2;
        rk += (ko<km)?1u:0u;
      }
      if(rk==off){ ans=m; break; }
    }
    out[t]=ans;
  }
}

__global__ void __launch_bounds__(1024,1) k_sel2(){
  extern __shared__ char smraw[];
  SelSm& s = *reinterpret_cast<SelSm*>(smraw);
  const int a = blockIdx.x;
  Key b42; b42.a=0u; b42.b=42u;
  Key ka  = split_p(b42,(u32)a);
  Key kr2 = split_p(ka,0);
  Key sub2= split_p(kr2,1);
  do_select(s, sub2, nullptr, g_p[a]);
}
__global__ void __launch_bounds__(1024,1) k_sel1(){
  extern __shared__ char smraw[];
  SelSm& s = *reinterpret_cast<SelSm*>(smraw);
  const int a = blockIdx.x;
  Key b42; b42.a=0u; b42.b=42u;
  Key ka  = split_p(b42,(u32)a);
  Key sub1= split_p(ka,1);
  do_select(s, sub1, g_p[a], g_idx[a]);
}

// ---- per-iteration RNG tables ----
__global__ void k_tables(){
  const int it = blockIdx.x, tid = threadIdx.x;
  Key base; base.a=0u; base.b=42u;
  Key kloop = split_p(base,4);
  Key kit   = split_p(kloop,(u32)it);
  Key ka    = split_p(kit,0);
  Key kb    = split_p(kit,1);
  Key kc    = split_p(kit,2);
  if(tid < 3*NB){
    Key pk  = split_p(ka,(u32)tid);
    Key sub = split_p(pk,1);
    u64 arr[NP];
    for(int i=0;i<NP;i++) arr[i] = ((u64)rbits_p(sub,(u32)i)<<6) | (u64)(u32)i;
    for(int i=1;i<NP;i++){
      u64 v = arr[i]; int j = i-1;
      while(j>=0 && arr[j]>v){ arr[j+1]=arr[j]; j--; }
      arr[j+1]=v;
    }
    int r = tid>>5, b = tid&31;
    for(int i=0;i<NP;i++) g_perm[it][r][b][i] = (unsigned char)(arr[i]&63u);
  }
  Key kr1 = split_p(kc,0);
  Key kr2 = split_p(kc,1);
  for(int f=tid; f<NB*NP; f+=blockDim.x){
    u32 hi = rbits_p(kr1,(u32)f);
    u32 lo = rbits_p(kr2,(u32)f);
    u32 jr = ((hi%6u)*4u + (lo%6u)) % 6u;
    unsigned char m = 0;
    for(int d=0; d<6; d++){
      float u = unif01(kb,(u32)(f*6+d));
      if(u < 0.9f || (u32)d == jr) m |= (unsigned char)(1<<d);
    }
    g_mask[it][f/NP][f%NP] = m;
  }
}

// ---- gather subsets + init population + barrier reset ----
__global__ void k_init(const float* __restrict__ source, const float* __restrict__ target){
  const int gid = blockIdx.x*blockDim.x + threadIdx.x;
  if(gid < NB) g_bar[gid] = 0;
  if(gid < NB*SUBN*3){
    int d = gid%3, i = (gid/3)%SUBN, b = gid/(3*SUBN);
    g_src[b][i][d] = source[((size_t)b*NPTS + g_idx[0][i])*3 + d];
    g_tgt[b][i][d] = target[((size_t)b*NPTS + g_idx[1][i])*3 + d];
  }
  if(gid < NB*NP*3){
    Key base; base.a=0u; base.b=42u;
    Key k2 = split_p(base,2);
    Key k3 = split_p(base,3);
    int d = gid%3, p = (gid/3)%NP, b = gid/(3*NP);
    float r = unif01(k2,(u32)gid);
    float t = unif01(k3,(u32)gid);
    r = fmaxf(-RRANGE, __fadd_rn(__fmul_rn(r, RRANGE+RRANGE), -RRANGE));
    t = fmaxf(-1.0f,   __fadd_rn(__fmul_rn(t, 2.0f), -1.0f));
    if(p==0){ r=0.0f; t=0.0f; }
    g_pop[0][b][p][d]   = r;
    g_pop[0][b][p][d+3] = t;
  }
}

// ---- rotation matrix (identical arithmetic to passing version) ----
__device__ void compute_R(const float* v, float* R){
  float v0=v[0], v1=v[1], v2=v[2];
  float n2 = __fadd_rn(__fadd_rn(__fmul_rn(v0,v0),__fmul_rn(v1,v1)),__fmul_rn(v2,v2));
  float th = __fsqrt_rn(n2);
  float dn = fmaxf(th, 1e-8f);
  float kx = __fdiv_rn(v0,dn), ky = __fdiv_rn(v1,dn), kz = __fdiv_rn(v2,dn);
  float s = sinf(th), c = cosf(th);
  float omc = __fsub_rn(1.0f, c);
  float K[9] = {0.f,-kz,ky,  kz,0.f,-kx,  -ky,kx,0.f};
#pragma unroll
  for(int i=0;i<3;i++)
#pragma unroll
    for(int j=0;j<3;j++){
      float kk = __fmaf_rn(K[i*3+2],K[2*3+j],
                 __fmaf_rn(K[i*3+1],K[1*3+j],
                 __fmul_rn(K[i*3+0],K[0*3+j])));
      float iden = (i==j)?1.0f:0.0f;
      float r = __fadd_rn(__fadd_rn(iden, __fmul_rn(s,K[i*3+j])), __fmul_rn(omc,kk));
      R[i*3+j] = (th < 1e-8f) ? iden : r;
    }
}

// Pair-interleaved shared tiles: one LDS.128 = two packed b64 operands.
struct Sh {
  ulonglong2 tA[SUBN/2];   // (2*t0 pair | 2*t1 pair)
  ulonglong2 tB[SUBN/2];   // (2*t2 pair | yn pair)
  ulonglong2 xA[SUBN/2];   // pose0: (x0 pair | x1 pair)
  ulonglong2 xB[SUBN/2];   // pose0: (x2 pair | xn pair)
  ulonglong2 wA[SUBN/2];   // pose1
  ulonglong2 wB[SUBN/2];
  float ra0[SUBN]; float ca0[SUBN];
  float ra1[SUBN]; float ca1[SUBN];
  float pose[12];
  float R[2][9];
  int imp[2];
};

__device__ __forceinline__ void bbar(int b, int n, int target){
  __syncthreads();
  if(n==0){
    __threadfence();
    atomicAdd(&g_bar[b], 1);
    while(atomicAdd(&g_bar[b], 0) < target) __nanosleep(64);
    __threadfence();
  }
  __syncthreads();
}

// fits valid on thread 0
__device__ void eval_both(Sh& sm, int n, float s0,float s1,float s2,
                          u64 nu0,u64 nu1,u64 nu2,u64 ynb,
                          float& f0, float& f1){
  float x0,x1,x2,xn, w0,w1,w2,wn;
  {
    const float* R = sm.R[0];
    x0 = __fadd_rn(__fmaf_rn(s2,R[2], __fmaf_rn(s1,R[1], __fmul_rn(s0,R[0]))), sm.pose[3]);
    x1 = __fadd_rn(__fmaf_rn(s2,R[5], __fmaf_rn(s1,R[4], __fmul_rn(s0,R[3]))), sm.pose[4]);
    x2 = __fadd_rn(__fmaf_rn(s2,R[8], __fmaf_rn(s1,R[7], __fmul_rn(s0,R[6]))), sm.pose[5]);
    xn = __fadd_rn(__fadd_rn(__fmul_rn(x0,x0),__fmul_rn(x1,x1)),__fmul_rn(x2,x2));
  }
  {
    const float* R = sm.R[1];
    w0 = __fadd_rn(__fmaf_rn(s2,R[2], __fmaf_rn(s1,R[1], __fmul_rn(s0,R[0]))), sm.pose[9]);
    w1 = __fadd_rn(__fmaf_rn(s2,R[5], __fmaf_rn(s1,R[4], __fmul_rn(s0,R[3]))), sm.pose[10]);
    w2 = __fadd_rn(__fmaf_rn(s2,R[8], __fmaf_rn(s1,R[7], __fmul_rn(s0,R[6]))), sm.pose[11]);
    wn = __fadd_rn(__fadd_rn(__fmul_rn(w0,w0),__fmul_rn(w1,w1)),__fmul_rn(w2,w2));
  }
  {
    int mp = n>>1, h = n&1;
    float* pA = (float*)&sm.xA[mp]; float* pB = (float*)&sm.xB[mp];
    pA[h] = x0; pA[2+h] = x1; pB[h] = x2; pB[2+h] = xn;
    float* qA = (float*)&sm.wA[mp]; float* qB = (float*)&sm.wB[mp];
    qA[h] = w0; qA[2+h] = w1; qB[h] = w2; qB[2+h] = wn;
  }
  // broadcasts: negated x/w (exact), duplicated norms
  u64 nx0=pack2(-x0,-x0), nx1=pack2(-x1,-x1), nx2=pack2(-x2,-x2), xnb=pack2(xn,xn);
  u64 nw0=pack2(-w0,-w0), nw1=pack2(-w1,-w1), nw2=pack2(-w2,-w2), wnb=pack2(wn,wn);
  __syncthreads();
  const float INF = __int_as_float(0x7f800000);
  float r0l=INF,r0h=INF, r1l=INF,r1h=INF, c0l=INF,c0h=INF, c1l=INF,c1h=INF;
#pragma unroll 4
  for(int mp=0;mp<SUBN/2;mp++){
    ulonglong2 a  = sm.tA[mp];
    ulonglong2 bb = sm.tB[mp];
    float lo,hi;
    // -dot2 = fma(-x2,t2d, fma(-x1,t1d, (-x0)*t0d));  d = (xn+yn) + (-dot2)
    u64 nd0 = fma2_(nx2, bb.x, fma2_(nx1, a.y, mul2(nx0, a.x)));
    unpack2(add2(add2(xnb, bb.y), nd0), lo, hi);
    r0l = fminf(r0l,lo); r0h = fminf(r0h,hi);
    u64 nd1 = fma2_(nw2, bb.x, fma2_(nw1, a.y, mul2(nw0, a.x)));
    unpack2(add2(add2(wnb, bb.y), nd1), lo, hi);
    r1l = fminf(r1l,lo); r1h = fminf(r1h,hi);
    ulonglong2 xa = sm.xA[mp];
    ulonglong2 xb = sm.xB[mp];
    u64 cd0 = fma2_(nu2, xb.x, fma2_(nu1, xa.y, mul2(nu0, xa.x)));
    unpack2(add2(add2(ynb, xb.y), cd0), lo, hi);
    c0l = fminf(c0l,lo); c0h = fminf(c0h,hi);
    ulonglong2 wa = sm.wA[mp];
    ulonglong2 wb = sm.wB[mp];
    u64 cd1 = fma2_(nu2, wb.x, fma2_(nu1, wa.y, mul2(nu0, wa.x)));
    unpack2(add2(add2(ynb, wb.y), cd1), lo, hi);
    c1l = fminf(c1l,lo); c1h = fminf(c1h,hi);
  }
  // clamp hoisted: min_m max(d,0) == max(min_m d, 0)
  sm.ra0[n] = fmaxf(fminf(r0l,r0h), 0.0f);
  sm.ca0[n] = fmaxf(fminf(c0l,c0h), 0.0f);
  sm.ra1[n] = fmaxf(fminf(r1l,r1h), 0.0f);
  sm.ca1[n] = fmaxf(fminf(c1l,c1h), 0.0f);
  __syncthreads();
  f0 = 0.0f; f1 = 0.0f;
  if(n < 32){
    float pr0 = __fadd_rn(__fadd_rn(__fadd_rn(sm.ra0[n], sm.ra0[n+32]), sm.ra0[n+64]), sm.ra0[n+96]);
    float pc0 = __fadd_rn(__fadd_rn(__fadd_rn(sm.ca0[n], sm.ca0[n+32]), sm.ca0[n+64]), sm.ca0[n+96]);
    float pr1 = __fadd_rn(__fadd_rn(__fadd_rn(sm.ra1[n], sm.ra1[n+32]), sm.ra1[n+64]), sm.ra1[n+96]);
    float pc1 = __fadd_rn(__fadd_rn(__fadd_rn(sm.ca1[n], sm.ca1[n+32]), sm.ca1[n+64]), sm.ca1[n+96]);
#pragma unroll
    for(int o=16;o>0;o>>=1){
      pr0 = __fadd_rn(pr0, __shfl_down_sync(0xffffffffu, pr0, o));
      pc0 = __fadd_rn(pc0, __shfl_down_sync(0xffffffffu, pc0, o));
      pr1 = __fadd_rn(pr1, __shfl_down_sync(0xffffffffu, pr1, o));
      pc1 = __fadd_rn(pc1, __shfl_down_sync(0xffffffffu, pc1, o));
    }
    f0 = __fadd_rn(__fmul_rn(pr0,0.0078125f), __fmul_rn(pc0,0.0078125f));
    f1 = __fadd_rn(__fmul_rn(pr1,0.0078125f), __fmul_rn(pc1,0.0078125f));
  }
}

// ---- persistent DE kernel: 2 particles per block, fused eval ----
__global__ void __launch_bounds__(SUBN, 6)
k_de(const float* __restrict__ source, float* __restrict__ out){
  __shared__ Sh sm;
  const int b = blockIdx.x / BPB, q = blockIdx.x % BPB, n = threadIdx.x;
  const int p0 = 2*q, p1 = 2*q+1;

  const float s0=g_src[b][n][0], s1=g_src[b][n][1], s2=g_src[b][n][2];
  const float u0=g_tgt[b][n][0], u1=g_tgt[b][n][1], u2=g_tgt[b][n][2];
  const float ynv = __fadd_rn(__fadd_rn(__fmul_rn(u0,u0),__fmul_rn(u1,u1)),__fmul_rn(u2,u2));
  const float u0d=__fadd_rn(u0,u0), u1d=__fadd_rn(u1,u1), u2d=__fadd_rn(u2,u2);
  {
    int mp = n>>1, h = n&1;
    float* pA = (float*)&sm.tA[mp]; float* pB = (float*)&sm.tB[mp];
    pA[h] = u0d; pA[2+h] = u1d; pB[h] = u2d; pB[2+h] = ynv;
  }
  const u64 nu0 = pack2(-u0d,-u0d), nu1 = pack2(-u1d,-u1d), nu2 = pack2(-u2d,-u2d);
  const u64 ynb = pack2(ynv,ynv);

  if(n<2){
    float* ps = sm.pose + 6*n;
    for(int d=0;d<6;d++) ps[d] = g_pop[0][b][p0+n][d];
    compute_R(ps, sm.R[n]);
  }
  __syncthreads();
  float f0,f1;
  eval_both(sm,n,s0,s1,s2,nu0,nu1,nu2,ynb,f0,f1);
  if(n==0){ g_fit[0][b][p0]=f0; g_fit[0][b][p1]=f1; }
  bbar(b,n,BPB*1);

  int sb = 0;
  for(int it=0; it<NIT; ++it){
    const int db = sb^1;
    if(n<2){
      const int p = p0 + n;
      float* ps = sm.pose + 6*n;
      int r1 = g_perm[it][0][b][p], r2 = g_perm[it][1][b][p], r3 = g_perm[it][2][b][p];
      unsigned char m = g_mask[it][b][p];
#pragma unroll
      for(int d=0;d<6;d++){
        float mu = __fadd_rn(g_pop[sb][b][r1][d],
                   __fmul_rn(0.8f, __fsub_rn(g_pop[sb][b][r2][d], g_pop[sb][b][r3][d])));
        float lim = (d<3) ? RRANGE : 1.0f;
        mu = fminf(fmaxf(mu, -lim), lim);
        ps[d] = ((m>>d)&1) ? mu : g_pop[sb][b][p][d];
      }
      compute_R(ps, sm.R[n]);
    }
    __syncthreads();
    float tf0,tf1;
    eval_both(sm,n,s0,s1,s2,nu0,nu1,nu2,ynb,tf0,tf1);
    if(n==0){
      float of0 = g_fit[sb][b][p0], of1 = g_fit[sb][b][p1];
      sm.imp[0] = (tf0 < of0);
      sm.imp[1] = (tf1 < of1);
      g_fit[db][b][p0] = sm.imp[0] ? tf0 : of0;
      g_fit[db][b][p1] = sm.imp[1] ? tf1 : of1;
    }
    __syncthreads();
    if(n<12){
      const int pp = n/6, d = n%6, p = p0 + pp;
      g_pop[db][b][p][d] = sm.imp[pp] ? sm.pose[n] : g_pop[sb][b][p][d];
    }
    bbar(b,n,BPB*(it+2));
    sb = db;
  }

  if(q==0 && n==0){
    float best = g_fit[sb][b][0]; int bi = 0;
    for(int pq=1;pq<NP;pq++){ float ff = g_fit[sb][b][pq]; if(ff < best){ best=ff; bi=pq; } }
    float pose[6];
    for(int d=0;d<6;d++) pose[d] = g_pop[sb][b][bi][d];
    float R[9]; compute_R(pose, R);
    for(int i=0;i<9;i++){ out[b*9+i] = R[i]; g_Rt[b][i] = R[i]; }
    for(int k=0;k<3;k++){ out[NB*9 + b*3 + k] = pose[3+k]; g_Rt[b][9+k] = pose[3+k]; }
  }
  bbar(b,n,BPB*(NIT+2));

  float Rt[12];
#pragma unroll
  for(int i=0;i<12;i++) Rt[i] = g_Rt[b][i];
  const int per = (NPTS + BPB - 1)/BPB;
  const int hi  = min((q+1)*per, NPTS);
  for(int i = q*per + n; i < hi; i += SUBN){
    const float* sp = source + ((size_t)b*NPTS + i)*3;
    float a0=sp[0], a1=sp[1], a2=sp[2];
    float* op = out + NB*12 + ((size_t)b*NPTS + i)*3;
#pragma unroll
    for(int k=0;k<3;k++){
      float dot = __fmaf_rn(a2, Rt[k*3+2],
                  __fmaf_rn(a1, Rt[k*3+1],
                  __fmul_rn(a0, Rt[k*3+0])));
      op[k] = __fadd_rn(dot, Rt[9+k]);
    }
  }
}

extern "C" void kernel_launch(void* const* d_in, const int* in_sizes, int n_in,
                              void* d_out, int out_size){
  (void)in_sizes; (void)n_in; (void)out_size;
  const float* source = (const float*)d_in[0];
  const float* target = (const float*)d_in[1];
  float* out = (float*)d_out;

  cudaFuncSetAttribute(k_sel2, cudaFuncAttributeMaxDynamicSharedMemorySize, (int)sizeof(SelSm));
  cudaFuncSetAttribute(k_sel1, cudaFuncAttributeMaxDynamicSharedMemorySize, (int)sizeof(SelSm));
  k_sel2<<<2, 1024, sizeof(SelSm)>>>();
  k_sel1<<<2, 1024, sizeof(SelSm)>>>();
  k_tables<<<NIT, 128>>>();
  k_init<<<(NB*SUBN*3 + 255)/256, 256>>>(source, target);
  k_de<<<NB*BPB, SUBN>>>(source, out);
}